// round 1
// baseline (speedup 1.0000x reference)
#include <cuda_runtime.h>
#include <cuda_bf16.h>

// out[i,j] = dot(z1[i], z2[j]) if batch[i]==batch[j] && cls[i]==cls[j]
//            && !(24<=cls[i]<=26) && i!=j, else 0.
// batch is sorted -> each row's valid j's live in a contiguous segment.
// One warp per output row: zero-fill the row (store-BW bound), then scatter
// the ~10 nonzero dot products into it.

__device__ __forceinline__ int lower_bound_dev(const int* __restrict__ a, int n, int v) {
    int lo = 0, hi = n;
    while (lo < hi) { int m = (lo + hi) >> 1; if (a[m] < v) lo = m + 1; else hi = m; }
    return lo;
}
__device__ __forceinline__ int upper_bound_dev(const int* __restrict__ a, int n, int v) {
    int lo = 0, hi = n;
    while (lo < hi) { int m = (lo + hi) >> 1; if (a[m] <= v) lo = m + 1; else hi = m; }
    return lo;
}

// Specialized for D == 128 (float4 per lane).
__global__ void seg_decoder_d128_kernel(const float* __restrict__ z1,
                                        const float* __restrict__ z2,
                                        const int*  __restrict__ cls,
                                        const int*  __restrict__ batch,
                                        float* __restrict__ out,
                                        int N)
{
    const int lane = threadIdx.x & 31;
    const int row  = (blockIdx.x * blockDim.x + threadIdx.x) >> 5;
    if (row >= N) return;

    // ---- Phase 1: zero this output row (fully coalesced float4 stream) ----
    float4* orow4 = reinterpret_cast<float4*>(out + (size_t)row * (size_t)N);
    const int n4 = N >> 2;
    const float4 z4 = make_float4(0.f, 0.f, 0.f, 0.f);
    #pragma unroll 4
    for (int k = lane; k < n4; k += 32) orow4[k] = z4;

    const int ci = cls[row];
    if (ci >= 24 && ci <= 26) return;   // whole row excluded -> stays zero
    const int bi = batch[row];

    // z1 row resident in registers: lane l holds elements [4l, 4l+4)
    const float4 a = reinterpret_cast<const float4*>(z1 + (size_t)row * 128)[lane];

    // Graph segment bounds in the sorted batch array (redundant per lane; cached).
    const int lo = lower_bound_dev(batch, N, bi);
    const int hi = upper_bound_dev(batch, N, bi);

    // Order the zero stores before the sparse overwrites (warp-level fence).
    __syncwarp();

    float* orow = out + (size_t)row * (size_t)N;
    for (int jb = lo; jb < hi; jb += 32) {
        const int j = jb + lane;
        const bool p = (j < hi) && (j != row) && (cls[j] == ci);
        unsigned m = __ballot_sync(0xffffffffu, p);
        while (m) {
            const int b = __ffs(m) - 1;
            m &= m - 1;
            const int jj = jb + b;
            const float4 v = reinterpret_cast<const float4*>(z2 + (size_t)jj * 128)[lane];
            float d = a.x * v.x + a.y * v.y + a.z * v.z + a.w * v.w;
            d += __shfl_xor_sync(0xffffffffu, d, 16);
            d += __shfl_xor_sync(0xffffffffu, d, 8);
            d += __shfl_xor_sync(0xffffffffu, d, 4);
            d += __shfl_xor_sync(0xffffffffu, d, 2);
            d += __shfl_xor_sync(0xffffffffu, d, 1);
            if (lane == 0) orow[jj] = d;
        }
    }
}

// Generic-D fallback (strided per-lane accumulation). Same structure.
__global__ void seg_decoder_generic_kernel(const float* __restrict__ z1,
                                           const float* __restrict__ z2,
                                           const int*  __restrict__ cls,
                                           const int*  __restrict__ batch,
                                           float* __restrict__ out,
                                           int N, int D)
{
    const int lane = threadIdx.x & 31;
    const int row  = (blockIdx.x * blockDim.x + threadIdx.x) >> 5;
    if (row >= N) return;

    float* orow = out + (size_t)row * (size_t)N;
    for (int k = lane; k < N; k += 32) orow[k] = 0.f;

    const int ci = cls[row];
    if (ci >= 24 && ci <= 26) return;
    const int bi = batch[row];

    const int lo = lower_bound_dev(batch, N, bi);
    const int hi = upper_bound_dev(batch, N, bi);

    const float* arow = z1 + (size_t)row * D;

    __syncwarp();

    for (int jb = lo; jb < hi; jb += 32) {
        const int j = jb + lane;
        const bool p = (j < hi) && (j != row) && (cls[j] == ci);
        unsigned m = __ballot_sync(0xffffffffu, p);
        while (m) {
            const int b = __ffs(m) - 1;
            m &= m - 1;
            const int jj = jb + b;
            const float* vrow = z2 + (size_t)jj * D;
            float d = 0.f;
            for (int k = lane; k < D; k += 32) d += arow[k] * vrow[k];
            d += __shfl_xor_sync(0xffffffffu, d, 16);
            d += __shfl_xor_sync(0xffffffffu, d, 8);
            d += __shfl_xor_sync(0xffffffffu, d, 4);
            d += __shfl_xor_sync(0xffffffffu, d, 2);
            d += __shfl_xor_sync(0xffffffffu, d, 1);
            if (lane == 0) orow[jj] = d;
        }
    }
}

extern "C" void kernel_launch(void* const* d_in, const int* in_sizes, int n_in,
                              void* d_out, int out_size)
{
    const float* z1    = (const float*)d_in[0];
    const float* z2    = (const float*)d_in[1];
    const int*   cls   = (const int*)d_in[2];
    const int*   batch = (const int*)d_in[3];
    float*       out   = (float*)d_out;

    const int N = in_sizes[2];                 // cls_label has N elements
    const int D = in_sizes[0] / N;             // z1 is N*D

    const int threads = 256;                   // 8 warps per block
    const int warps_needed = N;
    const int blocks = (warps_needed * 32 + threads - 1) / threads;

    if (D == 128 && (N & 3) == 0) {
        seg_decoder_d128_kernel<<<blocks, threads>>>(z1, z2, cls, batch, out, N);
    } else {
        seg_decoder_generic_kernel<<<blocks, threads>>>(z1, z2, cls, batch, out, N, D);
    }
}

// round 2
// speedup vs baseline: 1.0188x; 1.0188x over previous
#include <cuda_runtime.h>
#include <cuda_bf16.h>

// out[i,j] = dot(z1[i], z2[j]) if batch[i]==batch[j] && cls[i]==cls[j]
//            && !(24<=cls[i]<=26) && i!=j, else 0.
//
// Strategy: the output is ~99.9% zeros (sorted batch -> ~256-wide graph
// segments; ~1/27 class match rate). Phase 1: cudaMemsetAsync zero-fill of
// the whole 604MB output at driver-memset store bandwidth. Phase 2 (stream-
// ordered after): sparse scatter kernel computes the ~117k nonzero dot
// products and overwrites single entries.

__device__ __forceinline__ int lower_bound_dev(const int* __restrict__ a, int n, int v) {
    int lo = 0, hi = n;
    while (lo < hi) { int m = (lo + hi) >> 1; if (a[m] < v) lo = m + 1; else hi = m; }
    return lo;
}
__device__ __forceinline__ int upper_bound_dev(const int* __restrict__ a, int n, int v) {
    int lo = 0, hi = n;
    while (lo < hi) { int m = (lo + hi) >> 1; if (a[m] <= v) lo = m + 1; else hi = m; }
    return lo;
}

// Sparse scatter, specialized for D == 128 (float4 per lane).
// One warp per output row. Output row is already zeroed by the memset.
__global__ void seg_decoder_sparse_d128(const float* __restrict__ z1,
                                        const float* __restrict__ z2,
                                        const int*  __restrict__ cls,
                                        const int*  __restrict__ batch,
                                        float* __restrict__ out,
                                        int N)
{
    const int lane = threadIdx.x & 31;
    const int row  = (blockIdx.x * blockDim.x + threadIdx.x) >> 5;
    if (row >= N) return;

    const int ci = cls[row];
    if (ci >= 24 && ci <= 26) return;   // whole row excluded -> stays zero
    const int bi = batch[row];

    // z1 row resident in registers: lane l holds elements [4l, 4l+4)
    const float4 a = reinterpret_cast<const float4*>(z1 + (size_t)row * 128)[lane];

    // Graph segment bounds in the sorted batch array (L1/L2-resident).
    const int lo = lower_bound_dev(batch, N, bi);
    const int hi = upper_bound_dev(batch, N, bi);

    float* orow = out + (size_t)row * (size_t)N;
    for (int jb = lo; jb < hi; jb += 32) {
        const int j = jb + lane;
        const bool p = (j < hi) && (j != row) && (cls[j] == ci);
        unsigned m = __ballot_sync(0xffffffffu, p);
        while (m) {
            const int b = __ffs(m) - 1;
            m &= m - 1;
            const int jj = jb + b;
            const float4 v = reinterpret_cast<const float4*>(z2 + (size_t)jj * 128)[lane];
            float d = a.x * v.x + a.y * v.y + a.z * v.z + a.w * v.w;
            d += __shfl_xor_sync(0xffffffffu, d, 16);
            d += __shfl_xor_sync(0xffffffffu, d, 8);
            d += __shfl_xor_sync(0xffffffffu, d, 4);
            d += __shfl_xor_sync(0xffffffffu, d, 2);
            d += __shfl_xor_sync(0xffffffffu, d, 1);
            if (lane == 0) orow[jj] = d;
        }
    }
}

// Generic-D fallback (strided per-lane accumulation). Same structure.
__global__ void seg_decoder_sparse_generic(const float* __restrict__ z1,
                                           const float* __restrict__ z2,
                                           const int*  __restrict__ cls,
                                           const int*  __restrict__ batch,
                                           float* __restrict__ out,
                                           int N, int D)
{
    const int lane = threadIdx.x & 31;
    const int row  = (blockIdx.x * blockDim.x + threadIdx.x) >> 5;
    if (row >= N) return;

    const int ci = cls[row];
    if (ci >= 24 && ci <= 26) return;
    const int bi = batch[row];

    const int lo = lower_bound_dev(batch, N, bi);
    const int hi = upper_bound_dev(batch, N, bi);

    const float* arow = z1 + (size_t)row * D;
    float* orow = out + (size_t)row * (size_t)N;

    for (int jb = lo; jb < hi; jb += 32) {
        const int j = jb + lane;
        const bool p = (j < hi) && (j != row) && (cls[j] == ci);
        unsigned m = __ballot_sync(0xffffffffu, p);
        while (m) {
            const int b = __ffs(m) - 1;
            m &= m - 1;
            const int jj = jb + b;
            const float* vrow = z2 + (size_t)jj * D;
            float d = 0.f;
            for (int k = lane; k < D; k += 32) d += arow[k] * vrow[k];
            d += __shfl_xor_sync(0xffffffffu, d, 16);
            d += __shfl_xor_sync(0xffffffffu, d, 8);
            d += __shfl_xor_sync(0xffffffffu, d, 4);
            d += __shfl_xor_sync(0xffffffffu, d, 2);
            d += __shfl_xor_sync(0xffffffffu, d, 1);
            if (lane == 0) orow[jj] = d;
        }
    }
}

extern "C" void kernel_launch(void* const* d_in, const int* in_sizes, int n_in,
                              void* d_out, int out_size)
{
    const float* z1    = (const float*)d_in[0];
    const float* z2    = (const float*)d_in[1];
    const int*   cls   = (const int*)d_in[2];
    const int*   batch = (const int*)d_in[3];
    float*       out   = (float*)d_out;

    const int N = in_sizes[2];                 // cls_label has N elements
    const int D = in_sizes[0] / N;             // z1 is N*D

    // Phase 1: zero the whole output (store-bandwidth bound; driver memset
    // kernel achieves near-peak HBM write BW). Graph-capturable memset node.
    cudaMemsetAsync(out, 0, (size_t)out_size * sizeof(float));

    // Phase 2: sparse scatter of nonzero dot products (stream-ordered after).
    const int threads = 256;                   // 8 warps per block
    const int blocks = (N * 32 + threads - 1) / threads;

    if (D == 128) {
        seg_decoder_sparse_d128<<<blocks, threads>>>(z1, z2, cls, batch, out, N);
    } else {
        seg_decoder_sparse_generic<<<blocks, threads>>>(z1, z2, cls, batch, out, N, D);
    }
}